// round 14
// baseline (speedup 1.0000x reference)
#include <cuda_runtime.h>
#include <cstdint>

// RoiAlign 3D, shapes fixed:
//   features: [B=4, C=128, H=64, W=64, T=64] fp32
//   rois:     [R=512, 7] (y0,x0,z0,y1,x1,z1,bidx), coords in [0,64]
//   out:      [R=512, C=128, 7,7,7] fp32
//
// History:
//   R4 roi-fast grid, scalar 8-gather:      181.7us (DRAM 38.5, L1 71.8)
//   R5 smem staging:                        441us REGRESSED (2x smem port traffic)
//   R7 2 channels/block (16 LDG in flight): 138.0us (L1 86.5 = wall, DRAM 50)
//   R8 fused z0/z1 via aligned float4 row loads: z0,z1 live in the same
//      16B-aligned quad 75% of the time; one LDG.128 replaces two LDG.32
//      whose warp-level line sets were ~identical -> ~30% fewer L1 wavefronts.

#define RA_C   128
#define RA_DIM 64
#define RA_PTS 343   // 7*7*7

// select q[k], k in 0..3 (3 FSELs, no dynamic indexing)
__device__ __forceinline__ float q_at(float4 q, int k) {
    const float lo = (k & 1) ? q.y : q.x;
    const float hi = (k & 1) ? q.w : q.z;
    return (k & 2) ? hi : lo;
}

__global__ __launch_bounds__(352) void roi_align_kernel(
    const float* __restrict__ feat,
    const float* __restrict__ rois,
    float* __restrict__ out)
{
    const int r  = blockIdx.x;        // roi (fast dim -> cross-roi L2 reuse)
    const int c0 = blockIdx.y * 2;    // channel pair

    __shared__ int   s_i0[21];
    __shared__ float s_w[21];
    __shared__ int   s_b;

    const int tid = threadIdx.x;
    if (tid == 0) {
        s_b = (int)__ldg(&rois[r * 7 + 6]);
    }
    if (tid < 21) {
        const int axis = tid / 7;     // 0=y, 1=x, 2=z
        const int p    = tid % 7;
        const float lo = __ldg(&rois[r * 7 + axis])     * (1.0f / 64.0f);
        const float hi = __ldg(&rois[r * 7 + 3 + axis]) * (1.0f / 64.0f);
        const float step = (float)p / 6.0f;
        const float cc = lo * 63.0f + step * (hi - lo) * 63.0f;
        const float c0f = floorf(cc);
        int i0 = (int)c0f;
        i0 = min(max(i0, 0), RA_DIM - 1);
        s_i0[tid] = i0;
        s_w[tid]  = cc - c0f;
    }
    __syncthreads();

    if (tid >= RA_PTS) return;

    const int py  = tid / 49;
    const int rem = tid - py * 49;
    const int px  = rem / 7;
    const int pz  = rem - px * 7;

    const int   y0 = s_i0[py];
    const int   y1 = min(y0 + 1, RA_DIM - 1);
    const float wy = s_w[py];
    const int   x0 = s_i0[7 + px];
    const int   x1 = min(x0 + 1, RA_DIM - 1);
    const float wx = s_w[7 + px];
    const int   z0 = s_i0[14 + pz];
    const float wz = s_w[14 + pz];

    const int  k  = z0 & 3;          // position of z0 within its quad
    const int  zq = z0 & ~3;         // 16B-aligned quad base, always in-row
    const bool nq = (k == 3) && (z0 < RA_DIM - 1);  // z1 spills into next quad

    // base for (batch, channel): stride 64^3 = 1<<18 floats
    const float* fa  = feat + ((size_t)(s_b * RA_C + c0) << 18);
    const float* fbp = fa + ((size_t)1 << 18);      // channel c0+1

    // row offsets, addr(y,x,z) = (y<<12) + (x<<6) + z
    const int r00 = (y0 << 12) + (x0 << 6) + zq;
    const int r01 = (y0 << 12) + (x1 << 6) + zq;
    const int r10 = (y1 << 12) + (x0 << 6) + zq;
    const int r11 = (y1 << 12) + (x1 << 6) + zq;

    // 8 quad loads in flight (z0 & usually z1 in one access)
    const float4 qa00 = __ldg(reinterpret_cast<const float4*>(fa  + r00));
    const float4 qa01 = __ldg(reinterpret_cast<const float4*>(fa  + r01));
    const float4 qa10 = __ldg(reinterpret_cast<const float4*>(fa  + r10));
    const float4 qa11 = __ldg(reinterpret_cast<const float4*>(fa  + r11));
    const float4 qb00 = __ldg(reinterpret_cast<const float4*>(fbp + r00));
    const float4 qb01 = __ldg(reinterpret_cast<const float4*>(fbp + r01));
    const float4 qb10 = __ldg(reinterpret_cast<const float4*>(fbp + r10));
    const float4 qb11 = __ldg(reinterpret_cast<const float4*>(fbp + r11));

    // predicated next-quad scalars (only ~25% of threads, no wf from idle lanes)
    float sa00 = 0.f, sa01 = 0.f, sa10 = 0.f, sa11 = 0.f;
    float sb00 = 0.f, sb01 = 0.f, sb10 = 0.f, sb11 = 0.f;
    if (nq) {
        sa00 = __ldg(fa  + r00 + 4);
        sa01 = __ldg(fa  + r01 + 4);
        sa10 = __ldg(fa  + r10 + 4);
        sa11 = __ldg(fa  + r11 + 4);
        sb00 = __ldg(fbp + r00 + 4);
        sb01 = __ldg(fbp + r01 + 4);
        sb10 = __ldg(fbp + r10 + 4);
        sb11 = __ldg(fbp + r11 + 4);
    }

    // extract z0/z1 values
    const float a000 = q_at(qa00, k);
    const float a010 = q_at(qa01, k);
    const float a100 = q_at(qa10, k);
    const float a110 = q_at(qa11, k);
    const float b000 = q_at(qb00, k);
    const float b010 = q_at(qb01, k);
    const float b100 = q_at(qb10, k);
    const float b110 = q_at(qb11, k);

    const float a001 = (k < 3) ? q_at(qa00, k + 1) : (nq ? sa00 : a000);
    const float a011 = (k < 3) ? q_at(qa01, k + 1) : (nq ? sa01 : a010);
    const float a101 = (k < 3) ? q_at(qa10, k + 1) : (nq ? sa10 : a100);
    const float a111 = (k < 3) ? q_at(qa11, k + 1) : (nq ? sa11 : a110);
    const float b001 = (k < 3) ? q_at(qb00, k + 1) : (nq ? sb00 : b000);
    const float b011 = (k < 3) ? q_at(qb01, k + 1) : (nq ? sb01 : b010);
    const float b101 = (k < 3) ? q_at(qb10, k + 1) : (nq ? sb10 : b100);
    const float b111 = (k < 3) ? q_at(qb11, k + 1) : (nq ? sb11 : b110);

    const float iz = 1.0f - wz;
    const float ix = 1.0f - wx;
    const float iy = 1.0f - wy;

    const float a00 = iz * a000 + wz * a001;
    const float a01 = iz * a010 + wz * a011;
    const float a10 = iz * a100 + wz * a101;
    const float a11 = iz * a110 + wz * a111;
    const float b00 = iz * b000 + wz * b001;
    const float b01 = iz * b010 + wz * b011;
    const float b10 = iz * b100 + wz * b101;
    const float b11 = iz * b110 + wz * b111;

    const float a0 = ix * a00 + wx * a01;
    const float a1 = ix * a10 + wx * a11;
    const float b0 = ix * b00 + wx * b01;
    const float b1 = ix * b10 + wx * b11;

    float* ob = out + ((size_t)(r * RA_C + c0)) * RA_PTS;
    ob[tid]          = iy * a0 + wy * a1;
    ob[RA_PTS + tid] = iy * b0 + wy * b1;
}

extern "C" void kernel_launch(void* const* d_in, const int* in_sizes, int n_in,
                              void* d_out, int out_size)
{
    const float* feat = (const float*)d_in[0];
    const float* rois = (const float*)d_in[1];
    float* out = (float*)d_out;

    dim3 grid(512, RA_C / 2);   // roi fast, channel-pair slow
    roi_align_kernel<<<grid, 352>>>(feat, rois, out);
}